// round 8
// baseline (speedup 1.0000x reference)
#include <cuda_runtime.h>

// ----------------------------------------------------------------------------
// SymplecticGyroceptron — R8: R4 datapath + exact-fit persistent grid.
//
// R6/R7 lesson: every regression came from grid geometry (wave tails, CTA/SM
// imbalance), not the datapath. Fix: launch EXACTLY 4 CTAs per SM
// (grid = numSM*4, 256 thr, 64-reg cap -> 32 warps/SM resident) and have each
// thread loop over its 2-point pairs with a grid stride. Work per SM balances
// to ~0.1%; no partial waves.
//
// Datapath = R4 (best): per neuron per 2 pts
//   LDS.128 (wx,wy,b,wwx) + LDS.32 (wwy)   [10B/pt — lowest measured L1]
//   4 scalar FMA (pre-activations), 2 tanh.approx,
//   pack t -> 1 FFMA2 (t^2-1) -> 2 FFMA2 accumulate (weights packed via MOVs).
// wwx = -eps*wout*wx, wwy = -eps*wout*wy (negated: t^2-1 trick).
// ----------------------------------------------------------------------------

#define NEUR 64
#define NLAYERS 16   // 0..7 = psi (eps=1), 8..15 = ni (eps=0.01)
#define TPB 256

typedef unsigned long long u64;

__device__ float4 g_packedA[NLAYERS * NEUR];
__device__ float  g_packedB[NLAYERS * NEUR];
__device__ float2 g_eta[NLAYERS];
__device__ float2 g_cs;

__device__ __forceinline__ u64 pack2(float lo, float hi) {
    u64 d; asm("mov.b64 %0, {%1, %2};" : "=l"(d) : "f"(lo), "f"(hi)); return d;
}
__device__ __forceinline__ void unpack2(u64 d, float& lo, float& hi) {
    asm("mov.b64 {%0, %1}, %2;" : "=f"(lo), "=f"(hi) : "l"(d));
}
__device__ __forceinline__ u64 ffma2(u64 a, u64 b, u64 c) {
    u64 d; asm("fma.rn.f32x2 %0, %1, %2, %3;" : "=l"(d) : "l"(a), "l"(b), "l"(c));
    return d;
}
__device__ __forceinline__ float tanh_ap(float x) {
    float t; asm("tanh.approx.f32 %0, %1;" : "=f"(t) : "f"(x)); return t;
}

__global__ void prep_kernel(const float* __restrict__ theta0,
                            const float* __restrict__ psi_Win,
                            const float* __restrict__ psi_Wout,
                            const float* __restrict__ psi_b,
                            const float* __restrict__ psi_eta,
                            const float* __restrict__ ni_Win,
                            const float* __restrict__ ni_Wout,
                            const float* __restrict__ ni_b,
                            const float* __restrict__ ni_eta)
{
    int t = threadIdx.x;
    if (t < NLAYERS * NEUR) {
        int l = t >> 6;
        int j = t & 63;
        const float *Win, *Wout, *b;
        float eps;
        int i;
        if (l < 8) { i = l;     Win = psi_Win; Wout = psi_Wout; b = psi_b; eps = 1.0f;  }
        else       { i = l - 8; Win = ni_Win;  Wout = ni_Wout;  b = ni_b;  eps = 0.01f; }
        float w0 = Win[i * 128 + j];        // W_in[i][0][j]
        float w1 = Win[i * 128 + 64 + j];   // W_in[i][1][j]
        float bb = b[i * 64 + j];           // b_in[i][0][j]
        float wo = -Wout[i * 64 + j] * eps; // NEGATED eps*W_out (t^2-1 trick)
        g_packedA[t] = make_float4(w0, w1, bb, wo * w0);
        g_packedB[t] = wo * w1;
    }
    if (t < NLAYERS) {
        const float* e = (t < 8) ? (psi_eta + t * 2) : (ni_eta + (t - 8) * 2);
        g_eta[t] = make_float2(e[0], e[1]);
    }
    if (t == 0) {
        float th = theta0[0];
        g_cs = make_float2(cosf(th), sinf(th));
    }
}

// grad_V for two points (A,B). Scalar pre-activation, packed derivative+acc.
__device__ __forceinline__ void grad2x2(const float4* __restrict__ swA,
                                        const float*  __restrict__ swB,
                                        float yA0, float yA1,
                                        float yB0, float yB1,
                                        u64 NEG1,
                                        float& gA0, float& gA1,
                                        float& gB0, float& gB1)
{
    u64 acc0a = 0ull, acc1a = 0ull, acc0b = 0ull, acc1b = 0ull;
#pragma unroll 2
    for (int j = 0; j < NEUR; j += 2) {
        {
            float4 w  = swA[j];
            float  wy = swB[j];
            float pA = fmaf(yA0, w.x, fmaf(yA1, w.y, w.z));
            float pB = fmaf(yB0, w.x, fmaf(yB1, w.y, w.z));
            u64 tp  = pack2(tanh_ap(pA), tanh_ap(pB));
            u64 t2m = ffma2(tp, tp, NEG1);        // t^2 - 1
            acc0a = ffma2(t2m, pack2(w.w, w.w), acc0a);
            acc1a = ffma2(t2m, pack2(wy,  wy ), acc1a);
        }
        {
            float4 w  = swA[j + 1];
            float  wy = swB[j + 1];
            float pA = fmaf(yA0, w.x, fmaf(yA1, w.y, w.z));
            float pB = fmaf(yB0, w.x, fmaf(yB1, w.y, w.z));
            u64 tp  = pack2(tanh_ap(pA), tanh_ap(pB));
            u64 t2m = ffma2(tp, tp, NEG1);
            acc0b = ffma2(t2m, pack2(w.w, w.w), acc0b);
            acc1b = ffma2(t2m, pack2(wy,  wy ), acc1b);
        }
    }
    float a0A, a0B, b0A, b0B, a1A, a1B, b1A, b1B;
    unpack2(acc0a, a0A, a0B); unpack2(acc0b, b0A, b0B);
    unpack2(acc1a, a1A, a1B); unpack2(acc1b, b1A, b1B);
    gA0 = a0A + b0A;  gB0 = a0B + b0B;
    gA1 = a1A + b1A;  gB1 = a1B + b1B;
}

__global__ void __launch_bounds__(TPB, 4)
gyro_kernel(const float4* __restrict__ rin, float4* __restrict__ out,
            int B, int half)
{
    __shared__ float4 swA[NLAYERS * NEUR];
    __shared__ float  swB[NLAYERS * NEUR];
    __shared__ float2 seta[NLAYERS];
    __shared__ float2 scs;

    for (int i = threadIdx.x; i < NLAYERS * NEUR; i += TPB) {
        swA[i] = g_packedA[i];
        swB[i] = g_packedB[i];
    }
    if (threadIdx.x < NLAYERS) seta[threadIdx.x] = g_eta[threadIdx.x];
    if (threadIdx.x == 0)      scs = g_cs;
    __syncthreads();

    const u64 NEG1 = pack2(-1.0f, -1.0f);
    const int stride = gridDim.x * TPB;

    // Persistent loop: each thread handles pairs (p, p+half), p striding.
    for (int p = blockIdx.x * TPB + threadIdx.x; p < half; p += stride) {
        int p2 = p + half;
        bool hasB = (p2 < B);
        int c2 = hasB ? p2 : p;

        float4 zA = rin[p];
        float4 zB = rin[c2];
        float xA0 = zA.x, xA1 = zA.y, yA0 = zA.z, yA1 = zA.w;
        float xB0 = zB.x, xB1 = zB.y, yB0 = zB.z, yB1 = zB.w;

        // ---- inverse psi layers, l = 7 .. 0 ----
        for (int l = 7; l >= 0; --l) {
            float e0 = seta[l].x, e1 = seta[l].y;
            const float4* wA = &swA[l * NEUR];
            const float*  wB = &swB[l * NEUR];
#pragma unroll 1
            for (int k = 0; k < 4; ++k) {
                float ynA0 = xA0 - e0, ynA1 = xA1 - e1;
                float ynB0 = xB0 - e0, ynB1 = xB1 - e1;
                float gA0, gA1, gB0, gB1;
                grad2x2(wA, wB, ynA0, ynA1, ynB0, ynB1, NEG1, gA0, gA1, gB0, gB1);
                float nxA0 = gA0 - yA0, nxA1 = gA1 - yA1;
                float nxB0 = gB0 - yB0, nxB1 = gB1 - yB1;
                yA0 = ynA0; yA1 = ynA1; xA0 = nxA0; xA1 = nxA1;
                yB0 = ynB0; yB1 = ynB1; xB0 = nxB0; xB1 = nxB1;
            }
        }

        // ---- circle action ----
        {
            float c = scs.x, s = scs.y;
            float q1 = xA0, p1 = yA0;
            xA0 = fmaf(c, q1, s * p1);
            yA0 = fmaf(c, p1, -s * q1);
            q1 = xB0; p1 = yB0;
            xB0 = fmaf(c, q1, s * p1);
            yB0 = fmaf(c, p1, -s * q1);
        }

        // ---- forward layers: l = 0..7 psi, l = 8..15 ni ----
        for (int l = 0; l < NLAYERS; ++l) {
            float e0 = seta[l].x, e1 = seta[l].y;
            const float4* wA = &swA[l * NEUR];
            const float*  wB = &swB[l * NEUR];
#pragma unroll 1
            for (int k = 0; k < 4; ++k) {
                float gA0, gA1, gB0, gB1;
                grad2x2(wA, wB, yA0, yA1, yB0, yB1, NEG1, gA0, gA1, gB0, gB1);
                float nxA0 = yA0 + e0, nxA1 = yA1 + e1;
                float nyA0 = gA0 - xA0, nyA1 = gA1 - xA1;
                float nxB0 = yB0 + e0, nxB1 = yB1 + e1;
                float nyB0 = gB0 - xB0, nyB1 = gB1 - xB1;
                xA0 = nxA0; xA1 = nxA1; yA0 = nyA0; yA1 = nyA1;
                xB0 = nxB0; xB1 = nxB1; yB0 = nyB0; yB1 = nyB1;
            }
        }

        out[p] = make_float4(xA0, xA1, yA0, yA1);
        if (hasB)
            out[p2] = make_float4(xB0, xB1, yB0, yB1);
    }
}

extern "C" void kernel_launch(void* const* d_in, const int* in_sizes, int n_in,
                              void* d_out, int out_size)
{
    const float* r        = (const float*)d_in[0];
    const float* theta0   = (const float*)d_in[1];
    const float* psi_Win  = (const float*)d_in[2];
    const float* psi_Wout = (const float*)d_in[3];
    const float* psi_b    = (const float*)d_in[4];
    const float* psi_eta  = (const float*)d_in[5];
    const float* ni_Win   = (const float*)d_in[6];
    const float* ni_Wout  = (const float*)d_in[7];
    const float* ni_b     = (const float*)d_in[8];
    const float* ni_eta   = (const float*)d_in[9];

    int B = in_sizes[0] / 4;
    int half = (B + 1) / 2;

    prep_kernel<<<1, 1024>>>(theta0, psi_Win, psi_Wout, psi_b, psi_eta,
                             ni_Win, ni_Wout, ni_b, ni_eta);

    int sm = 148;
    cudaDeviceGetAttribute(&sm, cudaDevAttrMultiProcessorCount, 0);
    int blocks = sm * 4;                       // exact-fit: 4 CTAs per SM
    int maxBlocks = (half + TPB - 1) / TPB;    // never launch more than work
    if (blocks > maxBlocks) blocks = maxBlocks;
    gyro_kernel<<<blocks, TPB>>>((const float4*)r, (float4*)d_out, B, half);
}

// round 9
// speedup vs baseline: 1.2473x; 1.2473x over previous
#include <cuda_runtime.h>

// ----------------------------------------------------------------------------
// SymplecticGyroceptron — R9: R4 verbatim, launch_bounds (256,3) -> (256,4).
//
// R8 lesson: persistent loop + tight regs made ptxas marshal f32x2 register
// pairs with MOVs (alu 1.5%->15.9%, +30% issued work). So: single variable
// change from the best kernel (R4, 798us). Same loop structure, same unroll 4,
// only the occupancy cap moves 3->4 CTAs/SM (24->32 warps) via a 64-reg cap.
//
// Datapath (R4): per neuron per 2 pts
//   LDS.128 (wx,wy,b,wwx) + LDS.32 (wwy)   [10B/pt]
//   4 scalar FMA (pre), 2 tanh.approx, pack -> FFMA2 (t^2-1) -> 2 FFMA2 acc.
// wwx = -eps*wout*wx, wwy = -eps*wout*wy (negated: t^2-1 trick).
// ----------------------------------------------------------------------------

#define NEUR 64
#define NLAYERS 16   // 0..7 = psi (eps=1), 8..15 = ni (eps=0.01)

typedef unsigned long long u64;

__device__ float4 g_packedA[NLAYERS * NEUR];
__device__ float  g_packedB[NLAYERS * NEUR];
__device__ float2 g_eta[NLAYERS];
__device__ float2 g_cs;

__device__ __forceinline__ u64 pack2(float lo, float hi) {
    u64 d; asm("mov.b64 %0, {%1, %2};" : "=l"(d) : "f"(lo), "f"(hi)); return d;
}
__device__ __forceinline__ void unpack2(u64 d, float& lo, float& hi) {
    asm("mov.b64 {%0, %1}, %2;" : "=f"(lo), "=f"(hi) : "l"(d));
}
__device__ __forceinline__ u64 ffma2(u64 a, u64 b, u64 c) {
    u64 d; asm("fma.rn.f32x2 %0, %1, %2, %3;" : "=l"(d) : "l"(a), "l"(b), "l"(c));
    return d;
}
__device__ __forceinline__ float tanh_ap(float x) {
    float t; asm("tanh.approx.f32 %0, %1;" : "=f"(t) : "f"(x)); return t;
}

__global__ void prep_kernel(const float* __restrict__ theta0,
                            const float* __restrict__ psi_Win,
                            const float* __restrict__ psi_Wout,
                            const float* __restrict__ psi_b,
                            const float* __restrict__ psi_eta,
                            const float* __restrict__ ni_Win,
                            const float* __restrict__ ni_Wout,
                            const float* __restrict__ ni_b,
                            const float* __restrict__ ni_eta)
{
    int t = threadIdx.x;
    if (t < NLAYERS * NEUR) {
        int l = t >> 6;
        int j = t & 63;
        const float *Win, *Wout, *b;
        float eps;
        int i;
        if (l < 8) { i = l;     Win = psi_Win; Wout = psi_Wout; b = psi_b; eps = 1.0f;  }
        else       { i = l - 8; Win = ni_Win;  Wout = ni_Wout;  b = ni_b;  eps = 0.01f; }
        float w0 = Win[i * 128 + j];        // W_in[i][0][j]
        float w1 = Win[i * 128 + 64 + j];   // W_in[i][1][j]
        float bb = b[i * 64 + j];           // b_in[i][0][j]
        float wo = -Wout[i * 64 + j] * eps; // NEGATED eps*W_out (t^2-1 trick)
        g_packedA[t] = make_float4(w0, w1, bb, wo * w0);
        g_packedB[t] = wo * w1;
    }
    if (t < NLAYERS) {
        const float* e = (t < 8) ? (psi_eta + t * 2) : (ni_eta + (t - 8) * 2);
        g_eta[t] = make_float2(e[0], e[1]);
    }
    if (t == 0) {
        float th = theta0[0];
        g_cs = make_float2(cosf(th), sinf(th));
    }
}

// grad_V for two points simultaneously. Accumulators packed (A in lo, B in hi).
__device__ __forceinline__ void grad2x2(const float4* __restrict__ swA,
                                        const float*  __restrict__ swB,
                                        float yA0, float yA1,
                                        float yB0, float yB1,
                                        float& gA0, float& gA1,
                                        float& gB0, float& gB1)
{
    const u64 NEG1 = pack2(-1.0f, -1.0f);
    u64 acc0a = 0ull, acc1a = 0ull, acc0b = 0ull, acc1b = 0ull;
#pragma unroll 4
    for (int j = 0; j < NEUR; j += 2) {
        {
            float4 w  = swA[j];
            float  wy = swB[j];
            float pA = fmaf(yA0, w.x, fmaf(yA1, w.y, w.z));
            float pB = fmaf(yB0, w.x, fmaf(yB1, w.y, w.z));
            float tA = tanh_ap(pA);
            float tB = tanh_ap(pB);
            u64 tp  = pack2(tA, tB);
            u64 t2m = ffma2(tp, tp, NEG1);        // t^2 - 1
            acc0a = ffma2(t2m, pack2(w.w, w.w), acc0a);
            acc1a = ffma2(t2m, pack2(wy,  wy ), acc1a);
        }
        {
            float4 w  = swA[j + 1];
            float  wy = swB[j + 1];
            float pA = fmaf(yA0, w.x, fmaf(yA1, w.y, w.z));
            float pB = fmaf(yB0, w.x, fmaf(yB1, w.y, w.z));
            float tA = tanh_ap(pA);
            float tB = tanh_ap(pB);
            u64 tp  = pack2(tA, tB);
            u64 t2m = ffma2(tp, tp, NEG1);
            acc0b = ffma2(t2m, pack2(w.w, w.w), acc0b);
            acc1b = ffma2(t2m, pack2(wy,  wy ), acc1b);
        }
    }
    float a0A, a0B, b0A, b0B, a1A, a1B, b1A, b1B;
    unpack2(acc0a, a0A, a0B); unpack2(acc0b, b0A, b0B);
    unpack2(acc1a, a1A, a1B); unpack2(acc1b, b1A, b1B);
    gA0 = a0A + b0A;  gB0 = a0B + b0B;
    gA1 = a1A + b1A;  gB1 = a1B + b1B;
}

__global__ void __launch_bounds__(256, 4)
gyro_kernel(const float4* __restrict__ rin, float4* __restrict__ out,
            int B, int half)
{
    __shared__ float4 swA[NLAYERS * NEUR];
    __shared__ float  swB[NLAYERS * NEUR];
    __shared__ float2 seta[NLAYERS];
    __shared__ float2 scs;

    for (int i = threadIdx.x; i < NLAYERS * NEUR; i += blockDim.x) {
        swA[i] = g_packedA[i];
        swB[i] = g_packedB[i];
    }
    if (threadIdx.x < NLAYERS) seta[threadIdx.x] = g_eta[threadIdx.x];
    if (threadIdx.x == 0)      scs = g_cs;
    __syncthreads();

    int idx = blockIdx.x * blockDim.x + threadIdx.x;
    if (idx >= half) return;
    int idx2 = idx + half;
    bool hasB = (idx2 < B);
    int i2 = hasB ? idx2 : idx;

    float4 zA = rin[idx];
    float4 zB = rin[i2];
    float xA0 = zA.x, xA1 = zA.y, yA0 = zA.z, yA1 = zA.w;
    float xB0 = zB.x, xB1 = zB.y, yB0 = zB.z, yB1 = zB.w;

    // ---- inverse psi layers, l = 7 .. 0 ----
    for (int l = 7; l >= 0; --l) {
        float e0 = seta[l].x, e1 = seta[l].y;
        const float4* wA = &swA[l * NEUR];
        const float*  wB = &swB[l * NEUR];
#pragma unroll 1
        for (int k = 0; k < 4; ++k) {
            float ynA0 = xA0 - e0, ynA1 = xA1 - e1;
            float ynB0 = xB0 - e0, ynB1 = xB1 - e1;
            float gA0, gA1, gB0, gB1;
            grad2x2(wA, wB, ynA0, ynA1, ynB0, ynB1, gA0, gA1, gB0, gB1);
            float nxA0 = gA0 - yA0, nxA1 = gA1 - yA1;
            float nxB0 = gB0 - yB0, nxB1 = gB1 - yB1;
            yA0 = ynA0; yA1 = ynA1; xA0 = nxA0; xA1 = nxA1;
            yB0 = ynB0; yB1 = ynB1; xB0 = nxB0; xB1 = nxB1;
        }
    }

    // ---- circle action ----
    {
        float c = scs.x, s = scs.y;
        float q1 = xA0, p1 = yA0;
        xA0 = fmaf(c, q1, s * p1);
        yA0 = fmaf(c, p1, -s * q1);
        q1 = xB0; p1 = yB0;
        xB0 = fmaf(c, q1, s * p1);
        yB0 = fmaf(c, p1, -s * q1);
    }

    // ---- forward layers: l = 0..7 psi, l = 8..15 ni ----
    for (int l = 0; l < NLAYERS; ++l) {
        float e0 = seta[l].x, e1 = seta[l].y;
        const float4* wA = &swA[l * NEUR];
        const float*  wB = &swB[l * NEUR];
#pragma unroll 1
        for (int k = 0; k < 4; ++k) {
            float gA0, gA1, gB0, gB1;
            grad2x2(wA, wB, yA0, yA1, yB0, yB1, gA0, gA1, gB0, gB1);
            float nxA0 = yA0 + e0, nxA1 = yA1 + e1;
            float nyA0 = gA0 - xA0, nyA1 = gA1 - xA1;
            float nxB0 = yB0 + e0, nxB1 = yB1 + e1;
            float nyB0 = gB0 - xB0, nyB1 = gB1 - xB1;
            xA0 = nxA0; xA1 = nxA1; yA0 = nyA0; yA1 = nyA1;
            xB0 = nxB0; xB1 = nxB1; yB0 = nyB0; yB1 = nyB1;
        }
    }

    out[idx] = make_float4(xA0, xA1, yA0, yA1);
    if (hasB)
        out[idx2] = make_float4(xB0, xB1, yB0, yB1);
}

extern "C" void kernel_launch(void* const* d_in, const int* in_sizes, int n_in,
                              void* d_out, int out_size)
{
    const float* r        = (const float*)d_in[0];
    const float* theta0   = (const float*)d_in[1];
    const float* psi_Win  = (const float*)d_in[2];
    const float* psi_Wout = (const float*)d_in[3];
    const float* psi_b    = (const float*)d_in[4];
    const float* psi_eta  = (const float*)d_in[5];
    const float* ni_Win   = (const float*)d_in[6];
    const float* ni_Wout  = (const float*)d_in[7];
    const float* ni_b     = (const float*)d_in[8];
    const float* ni_eta   = (const float*)d_in[9];

    int B = in_sizes[0] / 4;
    int half = (B + 1) / 2;

    prep_kernel<<<1, 1024>>>(theta0, psi_Win, psi_Wout, psi_b, psi_eta,
                             ni_Win, ni_Wout, ni_b, ni_eta);

    int threads = 256;
    int blocks = (half + threads - 1) / threads;
    gyro_kernel<<<blocks, threads>>>((const float4*)r, (float4*)d_out, B, half);
}